// round 2
// baseline (speedup 1.0000x reference)
#include <cuda_runtime.h>

// Problem constants (fixed shapes)
#define NWIN      2048     // 8 * 16 * 16 windows
#define NTHREADS  512

// SMEM layout (float offsets). Token tiles stored transposed: [ch*68 + n]
// (stride 68 floats = 16B-aligned rows, bank-balanced for strided float4).
#define OFF_X1   0          // 256*68 = 17408
#define OFF_TP   17408      // 17408
#define OFF_QH   34816      // 64*68 = 4352  (reused as O)
#define OFF_KH   39168
#define OFF_VH   43520
#define OFF_SS   47872
#define OFF_WB   52224
#define OFF_MV   56576      // 64 mask values
#define OFF_KP   56640      // keep flag
#define SMEM_FLOATS 56644
#define SMEM_BYTES (SMEM_FLOATS * 4)   // 226,576 B  (< 227 KB opt-in limit)

__device__ float g_scale[256];
__device__ float g_shift[256];

// (64 tok x 64 out) = (64 tok x 256 ch) @ (64 out x 256 ch)^T
// Xs: token tile transposed [ch*68 + n]; Wrow0: 64 consecutive weight rows,
// row stride 256; wb: staging (stride 68); Os: output [n*68 + d].
__device__ __forceinline__ void tok_gemm(const float* __restrict__ Xs,
                                         const float* __restrict__ Wrow0,
                                         float* __restrict__ wb,
                                         float* __restrict__ Os, int t)
{
    const int d = t & 63, g = t >> 6;
    float acc[8];
#pragma unroll
    for (int j = 0; j < 8; j++) acc[j] = 0.f;

    for (int kc = 0; kc < 4; kc++) {
        __syncthreads();                 // prior wb readers done
#pragma unroll
        for (int i = 0; i < 2; i++) {    // stage 64x64 weight chunk
            int li = t + i * NTHREADS;   // over 1024 float4
            int dr = li >> 4, c4 = li & 15;
            float4 v = *(const float4*)(Wrow0 + dr * 256 + kc * 64 + c4 * 4);
            *(float4*)(wb + dr * 68 + c4 * 4) = v;
        }
        __syncthreads();
#pragma unroll
        for (int c4 = 0; c4 < 16; c4++) {
            float4 wv = *(const float4*)(wb + d * 68 + c4 * 4);
            int ch = kc * 64 + c4 * 4;
#pragma unroll
            for (int u = 0; u < 4; u++) {
                float w = (u == 0) ? wv.x : (u == 1) ? wv.y : (u == 2) ? wv.z : wv.w;
                float4 xa = *(const float4*)(Xs + (ch + u) * 68 + g * 8);
                float4 xb = *(const float4*)(Xs + (ch + u) * 68 + g * 8 + 4);
                acc[0] += xa.x * w; acc[1] += xa.y * w;
                acc[2] += xa.z * w; acc[3] += xa.w * w;
                acc[4] += xb.x * w; acc[5] += xb.y * w;
                acc[6] += xb.z * w; acc[7] += xb.w * w;
            }
        }
    }
#pragma unroll
    for (int j = 0; j < 8; j++) Os[(g * 8 + j) * 68 + d] = acc[j];
}

__global__ void __launch_bounds__(NTHREADS, 1)
attn_kernel(const float* __restrict__ pre, const float* __restrict__ pmask,
            const float* __restrict__ feat, const float* __restrict__ fmask,
            const float* __restrict__ mask,
            const float* __restrict__ qw, const float* __restrict__ kvw,
            const float* __restrict__ pw, const float* __restrict__ pb,
            float* __restrict__ out)
{
    extern __shared__ float sm[];
    float* sx1 = sm + OFF_X1;
    float* stp = sm + OFF_TP;
    float* Qh  = sm + OFF_QH;   // per-head Q, later reused as attention output O
    float* Kh  = sm + OFF_KH;
    float* Vh  = sm + OFF_VH;
    float* Ss  = sm + OFF_SS;
    float* wb  = sm + OFF_WB;
    float* mv  = sm + OFF_MV;
    float* kp  = sm + OFF_KP;

    const int t  = threadIdx.x;
    const int wi = blockIdx.x;
    const int b  = wi >> 8;
    const int hb = (wi >> 4) & 15;
    const int wbk = wi & 15;
    const int h0 = hb * 8, w0 = wbk * 8;

    // ---- resized mask per token (half-pixel bilinear 64->128, edge clamp) ----
    if (t < 64) {
        int r = t >> 3, cp = t & 7;
        int hh = h0 + r, ww = w0 + cp;
        float sh = 0.5f * hh - 0.25f;
        float sw = 0.5f * ww - 0.25f;
        float fsh = floorf(sh), fsw = floorf(sw);
        int hi = (int)fsh, wx = (int)fsw;
        float fh = sh - fsh, fw = sw - fsw;
        int hA = min(max(hi, 0), 63),      hB = min(max(hi + 1, 0), 63);
        int wA = min(max(wx, 0), 63),      wB = min(max(wx + 1, 0), 63);
        const float* mb = mask + b * 4096;
        float v = (1.f - fh) * ((1.f - fw) * mb[hA * 64 + wA] + fw * mb[hA * 64 + wB])
                +        fh  * ((1.f - fw) * mb[hB * 64 + wA] + fw * mb[hB * 64 + wB]);
        v *= fmask[hh * 128 + ww];
        mv[t] = v;
    }
    __syncthreads();
    if (t == 0) {
        float mx = mv[0];
        for (int i = 1; i < 64; i++) mx = fmaxf(mx, mv[i]);
        kp[0] = (mx >= 0.2f) ? 1.f : 0.f;
    }

    // ---- load x1 = feat*fmask and temp = pre*pmask*mask tiles (transposed) ----
#pragma unroll 4
    for (int i = 0; i < 32; i++) {
        int li = t + i * NTHREADS;      // over 16384: [ch][n], n fastest
        int ch = li >> 6, n = li & 63;
        int r = n >> 3, cp = n & 7;
        int hh = h0 + r, ww = w0 + cp;
        int gidx = ((b * 256 + ch) * 128 + hh) * 128 + ww;
        float fm = fmask[hh * 128 + ww];
        float pm = pmask[hh * 128 + ww];
        sx1[ch * 68 + n] = feat[gidx] * fm;
        stp[ch * 68 + n] = pre[gidx] * pm * mv[n];
    }

    float facc[32];                      // final[n=g*8+j][c = (t&63)+64*kk]
#pragma unroll
    for (int i = 0; i < 32; i++) facc[i] = 0.f;

    const int d = t & 63, g = t >> 6;

    for (int h = 0; h < 4; h++) {
        tok_gemm(sx1, qw  +  h * 64        * 256, wb, Qh, t);
        tok_gemm(stp, kvw +  h * 64        * 256, wb, Kh, t);
        tok_gemm(stp, kvw + (256 + h * 64) * 256, wb, Vh, t);
        __syncthreads();

        // ---- scores S[n][m] = 0.125 * Q[n]·K[m]   (d plays role of m) ----
        {
            float acc[8];
#pragma unroll
            for (int j = 0; j < 8; j++) acc[j] = 0.f;
#pragma unroll
            for (int d4 = 0; d4 < 16; d4++) {
                float4 kv = *(const float4*)(Kh + d * 68 + d4 * 4);
#pragma unroll
                for (int j = 0; j < 8; j++) {
                    float4 q = *(const float4*)(Qh + (g * 8 + j) * 68 + d4 * 4);
                    acc[j] += q.x * kv.x + q.y * kv.y + q.z * kv.z + q.w * kv.w;
                }
            }
#pragma unroll
            for (int j = 0; j < 8; j++) Ss[(g * 8 + j) * 68 + d] = acc[j] * 0.125f;
        }
        __syncthreads();

        // ---- row softmax ----
        if (t < 64) {
            float mx = -1e30f;
            for (int m = 0; m < 64; m++) mx = fmaxf(mx, Ss[t * 68 + m]);
            float sum = 0.f;
            for (int m = 0; m < 64; m++) {
                float e = __expf(Ss[t * 68 + m] - mx);
                Ss[t * 68 + m] = e; sum += e;
            }
            float inv = 1.f / sum;
            for (int m = 0; m < 64; m++) Ss[t * 68 + m] *= inv;
        }
        __syncthreads();

        // ---- O[n][d] = sum_m P[n][m] * V[m][d]  (write O into Qh) ----
        {
            float acc[8];
#pragma unroll
            for (int j = 0; j < 8; j++) acc[j] = 0.f;
#pragma unroll
            for (int m4 = 0; m4 < 16; m4++) {
                float v0 = Vh[(m4 * 4 + 0) * 68 + d];
                float v1 = Vh[(m4 * 4 + 1) * 68 + d];
                float v2 = Vh[(m4 * 4 + 2) * 68 + d];
                float v3 = Vh[(m4 * 4 + 3) * 68 + d];
#pragma unroll
                for (int j = 0; j < 8; j++) {
                    float4 p = *(const float4*)(Ss + (g * 8 + j) * 68 + m4 * 4);
                    acc[j] += p.x * v0 + p.y * v1 + p.z * v2 + p.w * v3;
                }
            }
#pragma unroll
            for (int j = 0; j < 8; j++) Qh[(g * 8 + j) * 68 + d] = acc[j];
        }
        __syncthreads();

        // ---- proj accumulate: final[n][c] += O[n]·proj_w[c, h*64:+64] ----
        for (int kk = 0; kk < 4; kk++) {
            __syncthreads();
#pragma unroll
            for (int i = 0; i < 2; i++) {
                int li = t + i * NTHREADS;
                int cc = li >> 4, d4 = li & 15;
                *(float4*)(wb + cc * 68 + d4 * 4) =
                    *(const float4*)(pw + (kk * 64 + cc) * 256 + h * 64 + d4 * 4);
            }
            __syncthreads();
#pragma unroll
            for (int d4 = 0; d4 < 16; d4++) {
                float4 wv = *(const float4*)(wb + d * 68 + d4 * 4);
#pragma unroll
                for (int j = 0; j < 8; j++) {
                    float4 o = *(const float4*)(Qh + (g * 8 + j) * 68 + d4 * 4);
                    facc[j * 4 + kk] += o.x * wv.x + o.y * wv.y + o.z * wv.z + o.w * wv.w;
                }
            }
        }
    }

    __syncthreads();
    const float keepf = kp[0];
#pragma unroll
    for (int kk = 0; kk < 4; kk++) {
        int c = d + 64 * kk;
        float bias = pb[c];
#pragma unroll
        for (int j = 0; j < 8; j++) {
            int n = g * 8 + j;            // n = g*8+j  =>  row r = g, col = j
            float v = (facc[j * 4 + kk] + bias) * keepf + sx1[c * 68 + n];
            out[((b * 256 + c) * 128 + (h0 + g)) * 128 + (w0 + j)] = v;
        }
    }
}

// ---------------- BatchNorm (training-mode batch statistics) ----------------

__global__ void bn_stats_kernel(const float* __restrict__ x,
                                const float* __restrict__ gamma,
                                const float* __restrict__ beta)
{
    __shared__ float rs[256], rss[256];
    const int c = blockIdx.x, t = threadIdx.x;
    float s = 0.f, ss = 0.f;
    for (int bb = 0; bb < 8; bb++) {
        const float4* p = (const float4*)(x + (size_t)(bb * 256 + c) * 16384);
        for (int i = t; i < 4096; i += 256) {
            float4 v = p[i];
            s  += v.x + v.y + v.z + v.w;
            ss += v.x * v.x + v.y * v.y + v.z * v.z + v.w * v.w;
        }
    }
    rs[t] = s; rss[t] = ss;
    __syncthreads();
    for (int o = 128; o > 0; o >>= 1) {
        if (t < o) { rs[t] += rs[t + o]; rss[t] += rss[t + o]; }
        __syncthreads();
    }
    if (t == 0) {
        const float inv_n = 1.f / 131072.f;
        float mean = rs[0] * inv_n;
        float var  = rss[0] * inv_n - mean * mean;
        float rstd = rsqrtf(var + 1e-5f);
        float sc = gamma[c] * rstd;
        g_scale[c] = sc;
        g_shift[c] = beta[c] - mean * sc;
    }
}

__global__ void bn_apply_kernel(float* __restrict__ x)
{
    int i = blockIdx.x * blockDim.x + threadIdx.x;   // over 8,388,608 float4
    int c = (i >> 12) & 255;                          // 4096 float4 per (b,c)
    float sc = g_scale[c], sh = g_shift[c];
    float4* p = (float4*)x;
    float4 v = p[i];
    v.x = v.x * sc + sh; v.y = v.y * sc + sh;
    v.z = v.z * sc + sh; v.w = v.w * sc + sh;
    p[i] = v;
}

// ------------------------------- launch --------------------------------------

extern "C" void kernel_launch(void* const* d_in, const int* in_sizes, int n_in,
                              void* d_out, int out_size)
{
    const float* pre   = (const float*)d_in[0];
    const float* pmask = (const float*)d_in[1];
    const float* feat  = (const float*)d_in[2];
    const float* fmask = (const float*)d_in[3];
    const float* mask  = (const float*)d_in[4];
    const float* qw    = (const float*)d_in[5];
    const float* kvw   = (const float*)d_in[6];
    const float* pw    = (const float*)d_in[7];
    const float* pb    = (const float*)d_in[8];
    const float* gamma = (const float*)d_in[9];
    const float* beta  = (const float*)d_in[10];
    float* out = (float*)d_out;

    cudaFuncSetAttribute(attn_kernel,
                         cudaFuncAttributeMaxDynamicSharedMemorySize, SMEM_BYTES);

    attn_kernel<<<NWIN, NTHREADS, SMEM_BYTES>>>(pre, pmask, feat, fmask, mask,
                                                qw, kvw, pw, pb, out);
    bn_stats_kernel<<<256, 256>>>(out, gamma, beta);
    bn_apply_kernel<<<32768, 256>>>(out);
}

// round 3
// speedup vs baseline: 1.0003x; 1.0003x over previous
#include <cuda_runtime.h>

// Problem constants (fixed shapes)
#define NWIN      2048     // 8 * 16 * 16 windows
#define NTHREADS  512

// SMEM layout (float offsets). Token tiles stored transposed: [ch*68 + n]
// (stride 68 floats = 16B-aligned rows, bank-balanced for strided float4).
#define OFF_X1   0          // 256*68 = 17408
#define OFF_TP   17408      // 17408
#define OFF_QH   34816      // 64*68 = 4352  (reused as O)
#define OFF_KH   39168
#define OFF_VH   43520
#define OFF_SS   47872
#define OFF_WB   52224
#define OFF_MV   56576      // 64 mask values
#define OFF_KP   56640      // keep flag
#define SMEM_FLOATS 56644
#define SMEM_BYTES (SMEM_FLOATS * 4)   // 226,576 B  (< 227 KB opt-in limit)

__device__ float g_scale[256];
__device__ float g_shift[256];

// (64 tok x 64 out) = (64 tok x 256 ch) @ (64 out x 256 ch)^T
// Xs: token tile transposed [ch*68 + n]; Wrow0: 64 consecutive weight rows,
// row stride 256; wb: staging (stride 68); Os: output [n*68 + d].
__device__ __forceinline__ void tok_gemm(const float* __restrict__ Xs,
                                         const float* __restrict__ Wrow0,
                                         float* __restrict__ wb,
                                         float* __restrict__ Os, int t)
{
    const int d = t & 63, g = t >> 6;
    float acc[8];
#pragma unroll
    for (int j = 0; j < 8; j++) acc[j] = 0.f;

    for (int kc = 0; kc < 4; kc++) {
        __syncthreads();                 // prior wb readers done
#pragma unroll
        for (int i = 0; i < 2; i++) {    // stage 64x64 weight chunk
            int li = t + i * NTHREADS;   // over 1024 float4
            int dr = li >> 4, c4 = li & 15;
            float4 v = *(const float4*)(Wrow0 + dr * 256 + kc * 64 + c4 * 4);
            *(float4*)(wb + dr * 68 + c4 * 4) = v;
        }
        __syncthreads();
#pragma unroll
        for (int c4 = 0; c4 < 16; c4++) {
            float4 wv = *(const float4*)(wb + d * 68 + c4 * 4);
            int ch = kc * 64 + c4 * 4;
#pragma unroll
            for (int u = 0; u < 4; u++) {
                float w = (u == 0) ? wv.x : (u == 1) ? wv.y : (u == 2) ? wv.z : wv.w;
                float4 xa = *(const float4*)(Xs + (ch + u) * 68 + g * 8);
                float4 xb = *(const float4*)(Xs + (ch + u) * 68 + g * 8 + 4);
                acc[0] += xa.x * w; acc[1] += xa.y * w;
                acc[2] += xa.z * w; acc[3] += xa.w * w;
                acc[4] += xb.x * w; acc[5] += xb.y * w;
                acc[6] += xb.z * w; acc[7] += xb.w * w;
            }
        }
    }
#pragma unroll
    for (int j = 0; j < 8; j++) Os[(g * 8 + j) * 68 + d] = acc[j];
}

__global__ void __launch_bounds__(NTHREADS, 1)
attn_kernel(const float* __restrict__ pre, const float* __restrict__ pmask,
            const float* __restrict__ feat, const float* __restrict__ fmask,
            const float* __restrict__ mask,
            const float* __restrict__ qw, const float* __restrict__ kvw,
            const float* __restrict__ pw, const float* __restrict__ pb,
            float* __restrict__ out)
{
    extern __shared__ float sm[];
    float* sx1 = sm + OFF_X1;
    float* stp = sm + OFF_TP;
    float* Qh  = sm + OFF_QH;   // per-head Q, later reused as attention output O
    float* Kh  = sm + OFF_KH;
    float* Vh  = sm + OFF_VH;
    float* Ss  = sm + OFF_SS;
    float* wb  = sm + OFF_WB;
    float* mv  = sm + OFF_MV;
    float* kp  = sm + OFF_KP;

    const int t  = threadIdx.x;
    const int wi = blockIdx.x;
    const int b  = wi >> 8;
    const int hb = (wi >> 4) & 15;
    const int wbk = wi & 15;
    const int h0 = hb * 8, w0 = wbk * 8;

    // ---- resized mask per token (half-pixel bilinear 64->128, edge clamp) ----
    if (t < 64) {
        int r = t >> 3, cp = t & 7;
        int hh = h0 + r, ww = w0 + cp;
        float sh = 0.5f * hh - 0.25f;
        float sw = 0.5f * ww - 0.25f;
        float fsh = floorf(sh), fsw = floorf(sw);
        int hi = (int)fsh, wx = (int)fsw;
        float fh = sh - fsh, fw = sw - fsw;
        int hA = min(max(hi, 0), 63),      hB = min(max(hi + 1, 0), 63);
        int wA = min(max(wx, 0), 63),      wB = min(max(wx + 1, 0), 63);
        const float* mb = mask + b * 4096;
        float v = (1.f - fh) * ((1.f - fw) * mb[hA * 64 + wA] + fw * mb[hA * 64 + wB])
                +        fh  * ((1.f - fw) * mb[hB * 64 + wA] + fw * mb[hB * 64 + wB]);
        v *= fmask[hh * 128 + ww];
        mv[t] = v;
    }
    __syncthreads();
    if (t == 0) {
        float mx = mv[0];
        for (int i = 1; i < 64; i++) mx = fmaxf(mx, mv[i]);
        kp[0] = (mx >= 0.2f) ? 1.f : 0.f;
    }

    // ---- load x1 = feat*fmask and temp = pre*pmask*mask tiles (transposed) ----
#pragma unroll 4
    for (int i = 0; i < 32; i++) {
        int li = t + i * NTHREADS;      // over 16384: [ch][n], n fastest
        int ch = li >> 6, n = li & 63;
        int r = n >> 3, cp = n & 7;
        int hh = h0 + r, ww = w0 + cp;
        int gidx = ((b * 256 + ch) * 128 + hh) * 128 + ww;
        float fm = fmask[hh * 128 + ww];
        float pm = pmask[hh * 128 + ww];
        sx1[ch * 68 + n] = feat[gidx] * fm;
        stp[ch * 68 + n] = pre[gidx] * pm * mv[n];
    }

    float facc[32];                      // final[n=g*8+j][c = (t&63)+64*kk]
#pragma unroll
    for (int i = 0; i < 32; i++) facc[i] = 0.f;

    const int d = t & 63, g = t >> 6;

    for (int h = 0; h < 4; h++) {
        tok_gemm(sx1, qw  +  h * 64        * 256, wb, Qh, t);
        tok_gemm(stp, kvw +  h * 64        * 256, wb, Kh, t);
        tok_gemm(stp, kvw + (256 + h * 64) * 256, wb, Vh, t);
        __syncthreads();

        // ---- scores S[n][m] = 0.125 * Q[n]·K[m]   (d plays role of m) ----
        {
            float acc[8];
#pragma unroll
            for (int j = 0; j < 8; j++) acc[j] = 0.f;
#pragma unroll
            for (int d4 = 0; d4 < 16; d4++) {
                float4 kv = *(const float4*)(Kh + d * 68 + d4 * 4);
#pragma unroll
                for (int j = 0; j < 8; j++) {
                    float4 q = *(const float4*)(Qh + (g * 8 + j) * 68 + d4 * 4);
                    acc[j] += q.x * kv.x + q.y * kv.y + q.z * kv.z + q.w * kv.w;
                }
            }
#pragma unroll
            for (int j = 0; j < 8; j++) Ss[(g * 8 + j) * 68 + d] = acc[j] * 0.125f;
        }
        __syncthreads();

        // ---- row softmax ----
        if (t < 64) {
            float mx = -1e30f;
            for (int m = 0; m < 64; m++) mx = fmaxf(mx, Ss[t * 68 + m]);
            float sum = 0.f;
            for (int m = 0; m < 64; m++) {
                float e = __expf(Ss[t * 68 + m] - mx);
                Ss[t * 68 + m] = e; sum += e;
            }
            float inv = 1.f / sum;
            for (int m = 0; m < 64; m++) Ss[t * 68 + m] *= inv;
        }
        __syncthreads();

        // ---- O[n][d] = sum_m P[n][m] * V[m][d]  (write O into Qh) ----
        {
            float acc[8];
#pragma unroll
            for (int j = 0; j < 8; j++) acc[j] = 0.f;
#pragma unroll
            for (int m4 = 0; m4 < 16; m4++) {
                float v0 = Vh[(m4 * 4 + 0) * 68 + d];
                float v1 = Vh[(m4 * 4 + 1) * 68 + d];
                float v2 = Vh[(m4 * 4 + 2) * 68 + d];
                float v3 = Vh[(m4 * 4 + 3) * 68 + d];
#pragma unroll
                for (int j = 0; j < 8; j++) {
                    float4 p = *(const float4*)(Ss + (g * 8 + j) * 68 + m4 * 4);
                    acc[j] += p.x * v0 + p.y * v1 + p.z * v2 + p.w * v3;
                }
            }
#pragma unroll
            for (int j = 0; j < 8; j++) Qh[(g * 8 + j) * 68 + d] = acc[j];
        }
        __syncthreads();

        // ---- proj accumulate: final[n][c] += O[n]·proj_w[c, h*64:+64] ----
        for (int kk = 0; kk < 4; kk++) {
            __syncthreads();
#pragma unroll
            for (int i = 0; i < 2; i++) {
                int li = t + i * NTHREADS;
                int cc = li >> 4, d4 = li & 15;
                *(float4*)(wb + cc * 68 + d4 * 4) =
                    *(const float4*)(pw + (kk * 64 + cc) * 256 + h * 64 + d4 * 4);
            }
            __syncthreads();
#pragma unroll
            for (int d4 = 0; d4 < 16; d4++) {
                float4 wv = *(const float4*)(wb + d * 68 + d4 * 4);
#pragma unroll
                for (int j = 0; j < 8; j++) {
                    float4 o = *(const float4*)(Qh + (g * 8 + j) * 68 + d4 * 4);
                    facc[j * 4 + kk] += o.x * wv.x + o.y * wv.y + o.z * wv.z + o.w * wv.w;
                }
            }
        }
    }

    __syncthreads();
    const float keepf = kp[0];
#pragma unroll
    for (int kk = 0; kk < 4; kk++) {
        int c = d + 64 * kk;
        float bias = pb[c];
#pragma unroll
        for (int j = 0; j < 8; j++) {
            int n = g * 8 + j;            // n = g*8+j  =>  row r = g, col = j
            float v = (facc[j * 4 + kk] + bias) * keepf + sx1[c * 68 + n];
            out[((b * 256 + c) * 128 + (h0 + g)) * 128 + (w0 + j)] = v;
        }
    }
}

// ---------------- BatchNorm (training-mode batch statistics) ----------------

__global__ void bn_stats_kernel(const float* __restrict__ x,
                                const float* __restrict__ gamma,
                                const float* __restrict__ beta)
{
    __shared__ float rs[256], rss[256];
    const int c = blockIdx.x, t = threadIdx.x;
    float s = 0.f, ss = 0.f;
    for (int bb = 0; bb < 8; bb++) {
        const float4* p = (const float4*)(x + (size_t)(bb * 256 + c) * 16384);
        for (int i = t; i < 4096; i += 256) {
            float4 v = p[i];
            s  += v.x + v.y + v.z + v.w;
            ss += v.x * v.x + v.y * v.y + v.z * v.z + v.w * v.w;
        }
    }
    rs[t] = s; rss[t] = ss;
    __syncthreads();
    for (int o = 128; o > 0; o >>= 1) {
        if (t < o) { rs[t] += rs[t + o]; rss[t] += rss[t + o]; }
        __syncthreads();
    }
    if (t == 0) {
        const float inv_n = 1.f / 131072.f;
        float mean = rs[0] * inv_n;
        float var  = rss[0] * inv_n - mean * mean;
        float rstd = rsqrtf(var + 1e-5f);
        float sc = gamma[c] * rstd;
        g_scale[c] = sc;
        g_shift[c] = beta[c] - mean * sc;
    }
}

__global__ void bn_apply_kernel(float* __restrict__ x)
{
    int i = blockIdx.x * blockDim.x + threadIdx.x;   // over 8,388,608 float4
    int c = (i >> 12) & 255;                          // 4096 float4 per (b,c)
    float sc = g_scale[c], sh = g_shift[c];
    float4* p = (float4*)x;
    float4 v = p[i];
    v.x = v.x * sc + sh; v.y = v.y * sc + sh;
    v.z = v.z * sc + sh; v.w = v.w * sc + sh;
    p[i] = v;
}

// ------------------------------- launch --------------------------------------

extern "C" void kernel_launch(void* const* d_in, const int* in_sizes, int n_in,
                              void* d_out, int out_size)
{
    const float* pre   = (const float*)d_in[0];
    const float* pmask = (const float*)d_in[1];
    const float* feat  = (const float*)d_in[2];
    const float* fmask = (const float*)d_in[3];
    const float* mask  = (const float*)d_in[4];
    const float* qw    = (const float*)d_in[5];
    const float* kvw   = (const float*)d_in[6];
    const float* pw    = (const float*)d_in[7];
    const float* pb    = (const float*)d_in[8];
    const float* gamma = (const float*)d_in[9];
    const float* beta  = (const float*)d_in[10];
    float* out = (float*)d_out;

    cudaFuncSetAttribute(attn_kernel,
                         cudaFuncAttributeMaxDynamicSharedMemorySize, SMEM_BYTES);

    attn_kernel<<<NWIN, NTHREADS, SMEM_BYTES>>>(pre, pmask, feat, fmask, mask,
                                                qw, kvw, pw, pb, out);
    bn_stats_kernel<<<256, 256>>>(out, gamma, beta);
    bn_apply_kernel<<<32768, 256>>>(out);
}